// round 11
// baseline (speedup 1.0000x reference)
#include <cuda_runtime.h>
#include <math.h>
#include <stdint.h>

#define B 4
#define S 2048
#define D 1024
#define H 16
#define DH 64
#define M (B * S)          // 8192
#define EPS 1e-5f

// ---------------- scratch: gmem tile images (fragment-major) ---------------
// X tiles  [kt32][mb64][3072]: rg8 x lane32(stride12) x ks2*4+j   (A-frag)
__device__ uint32_t g_xk[(size_t)32 * 64 * 3072];
// QKV W tiles [h][kt32][3072]: nblk24 x ks2 x lane32 x 2          (B-frag)
__device__ uint32_t g_wqk[(size_t)H * 32 * 3072];
// Wo tiles [nb8][kt32][16][136] (row-major, unchanged from R9)
__device__ uint32_t g_wok[(size_t)8 * 32 * 16 * 136];
// Q tiles [bh][qt16][5120]: rg8 x lane32(stride20) x ks4*4+j      (A-frag)
__device__ uint32_t g_qk[(size_t)B * H * 16 * 5120];
// K tiles [bh][st32][2048]: nblk8 x ks4 x lane32 x 2              (B-frag)
__device__ uint32_t g_kk[(size_t)B * H * 32 * 2048];
// V raw [bh][s][dhp]
__device__ uint32_t g_vh[(size_t)B * H * S * 32];
// V tiles [bh][st32][2048]: nblk8 x ks4 x lane32 x 2              (B-frag)
__device__ uint32_t g_vk[(size_t)B * H * 32 * 2048];
// ctx tiles [kt][m][20] (row-major, unchanged; consumed by proj)
__device__ uint32_t g_ctk[(size_t)32 * M * 20];
__device__ float    g_tmp[(size_t)B * S * D];

// ---------------- helpers ----------------
__device__ __forceinline__ uint32_t f2bf2(float lo, float hi) {
    uint32_t d;
    asm("cvt.rn.bf16x2.f32 %0, %1, %2;" : "=r"(d) : "f"(hi), "f"(lo));
    return d;
}
__device__ __forceinline__ uint32_t prmt(uint32_t a, uint32_t b, uint32_t s) {
    uint32_t d;
    asm("prmt.b32 %0, %1, %2, %3;" : "=r"(d) : "r"(a), "r"(b), "r"(s));
    return d;
}
__device__ __forceinline__ uint32_t sm2u(const void* p) {
    return (uint32_t)__cvta_generic_to_shared(p);
}
__device__ __forceinline__ void mbar_init(uint32_t a, uint32_t cnt) {
    asm volatile("mbarrier.init.shared.b64 [%0], %1;" :: "r"(a), "r"(cnt) : "memory");
}
__device__ __forceinline__ void mbar_expect(uint32_t a, uint32_t bytes) {
    asm volatile("mbarrier.arrive.expect_tx.shared.b64 _, [%0], %1;"
                 :: "r"(a), "r"(bytes) : "memory");
}
__device__ __forceinline__ void mbar_wait(uint32_t a, int ph) {
    asm volatile(
        "{\n\t.reg .pred P;\n\t"
        "WL%=:\n\t"
        "mbarrier.try_wait.parity.shared::cta.b64 P, [%0], %1;\n\t"
        "@P bra WD%=;\n\t"
        "bra WL%=;\n\t"
        "WD%=:\n\t}"
        :: "r"(a), "r"(ph) : "memory");
}
__device__ __forceinline__ void bulkcp(uint32_t dst, const void* src,
                                       uint32_t bytes, uint32_t mbar) {
    asm volatile(
        "cp.async.bulk.shared::cluster.global.mbarrier::complete_tx::bytes "
        "[%0], [%1], %2, [%3];"
        :: "r"(dst), "l"(src), "r"(bytes), "r"(mbar) : "memory");
}
#define FENCE_ASYNC() asm volatile("fence.proxy.async.shared::cta;" ::: "memory")

// D = A(16x16,row) * B(16x8,col) + D, bf16 in, f32 accum
__device__ __forceinline__ void mma16(float4& c, const uint32_t a[4],
                                      uint32_t b0, uint32_t b1) {
    asm volatile(
        "mma.sync.aligned.m16n8k16.row.col.f32.bf16.bf16.f32 "
        "{%0,%1,%2,%3}, {%4,%5,%6,%7}, {%8,%9}, {%0,%1,%2,%3};"
        : "+f"(c.x), "+f"(c.y), "+f"(c.z), "+f"(c.w)
        : "r"(a[0]), "r"(a[1]), "r"(a[2]), "r"(a[3]), "r"(b0), "r"(b1));
}

// ============================================================================
// Prologue packers.
// ============================================================================
__global__ __launch_bounds__(256) void cvt_x_kernel(const float* __restrict__ x)
{
    int idx = blockIdx.x * 256 + threadIdx.x;       // over M*512
    int m = idx >> 9, dp = idx & 511;
    float2 v = *(const float2*)&x[(size_t)idx * 2];
    int kt = dp >> 4, kp = dp & 15;
    int mb = m >> 7, r = m & 127;
    int widx = (r >> 4) * 384 + ((r & 7) * 4 + (kp & 3)) * 12
             + (kp >> 3) * 4 + ((r >> 3) & 1) + 2 * ((kp >> 2) & 1);
    g_xk[((size_t)kt * 64 + mb) * 3072 + widx] = f2bf2(v.x, v.y);
}

__global__ __launch_bounds__(256) void cvt_wqkv_kernel(
    const float* __restrict__ Wq,
    const float* __restrict__ Wk,
    const float* __restrict__ Wv)
{
    int idx = blockIdx.x * 256 + threadIdx.x;       // over H*512*192
    int n  = idx % 192;
    int kp = (idx / 192) & 511;
    int h  = idx / (192 * 512);
    int z = n >> 6, dh = n & 63;
    const float* W = (z == 0) ? Wq : (z == 1) ? Wk : Wv;
    size_t base = ((size_t)h * D + 2 * kp) * DH + dh;
    uint32_t val = f2bf2(W[base], W[base + DH]);
    int kt = kp >> 4, kpi = kp & 15;
    int widx = (((n >> 3) * 2 + (kpi >> 3)) * 32 + (n & 7) * 4 + (kpi & 3)) * 2
             + ((kpi >> 2) & 1);
    g_wqk[((size_t)h * 32 + kt) * 3072 + widx] = val;
}

__global__ __launch_bounds__(256) void cvt_wo_kernel(const float* __restrict__ Wo)
{
    int idx = blockIdx.x * 256 + threadIdx.x;       // over 512*1024
    int n = idx & 1023;
    int kp = idx >> 10;
    g_wok[(((size_t)(n >> 7) * 32 + (kp >> 4)) * 16 + (kp & 15)) * 136 + (n & 127)] =
        f2bf2(Wo[(size_t)(2 * kp) * 1024 + n], Wo[(size_t)(2 * kp + 1) * 1024 + n]);
}

// V transpose: raw [bh][s][dhp] -> B-frag tiles [bh][st][2048]
__global__ __launch_bounds__(256) void vtr_kernel()
{
    int idx = blockIdx.x * 256 + threadIdx.x;       // over B*H*1024*32
    int dp = idx & 31;                               // dh pair 0..31
    int sp = (idx >> 5) & 1023;
    int bh = idx >> 15;
    uint32_t va = g_vh[((size_t)bh * S + 2 * sp) * 32 + dp];
    uint32_t vb = g_vh[((size_t)bh * S + 2 * sp + 1) * 32 + dp];
    uint32_t w0 = prmt(va, vb, 0x5410);   // dh = 2*dp
    uint32_t w1 = prmt(va, vb, 0x7632);   // dh = 2*dp+1
    int st = sp >> 5, spi = sp & 31;
    int ks = spi >> 3, tqv = spi & 3, half = (spi >> 2) & 1;
    size_t tb = ((size_t)bh * 32 + st) * 2048;
    int dh0 = 2 * dp;
    g_vk[tb + (((dh0 >> 3) * 4 + ks) * 32 + (dh0 & 7) * 4 + tqv) * 2 + half] = w0;
    int dh1 = 2 * dp + 1;
    g_vk[tb + (((dh1 >> 3) * 4 + ks) * 32 + (dh1 & 7) * 4 + tqv) * 2 + half] = w1;
}

// ============================================================================
// Kernel 1: QKV projection, z-folded, bulk-copy + fragment-major tiles.
// grid (M/128, H), block 512, 16 warps 4m x 4n, warp tile 32x48.
// ============================================================================
#define QKV_XB (3072 * 4)
#define QKV_WB (3072 * 4)

__global__ __launch_bounds__(512, 2) void qkv_tc()
{
    __shared__ __align__(16) uint32_t Xs[2][3072];
    __shared__ __align__(16) uint32_t Wp[2][3072];
    __shared__ __align__(8)  uint64_t mb[2];

    const int m0 = blockIdx.x * 128;
    const int h  = blockIdx.y;

    const int tid = threadIdx.x;
    const int w = tid >> 5, lane = tid & 31;
    const int g = lane >> 2, tq = lane & 3;
    const int wm = w >> 2, wn = w & 3;

    const uint32_t mbA0 = sm2u(&mb[0]), mbA1 = sm2u(&mb[1]);
    if (tid == 0) { mbar_init(mbA0, 1); mbar_init(mbA1, 1); }
    FENCE_ASYNC();
    __syncthreads();

    auto produce = [&](int s, int kt) {
        if (tid == 0) {
            uint32_t mba = s ? mbA1 : mbA0;
            mbar_expect(mba, QKV_XB + QKV_WB);
            bulkcp(sm2u(&Xs[s][0]),
                   &g_xk[((size_t)kt * 64 + (m0 >> 7)) * 3072], QKV_XB, mba);
            bulkcp(sm2u(&Wp[s][0]),
                   &g_wqk[((size_t)h * 32 + kt) * 3072], QKV_WB, mba);
        }
    };

    float4 acc[2][6];
    #pragma unroll
    for (int i = 0; i < 2; i++)
        #pragma unroll
        for (int j = 0; j < 6; j++) acc[i][j] = make_float4(0.f, 0.f, 0.f, 0.f);

    int ph0 = 0, ph1 = 0;
    produce(0, 0);

    for (int kt = 0; kt < 32; kt++) {
        const int s = kt & 1;
        if (kt + 1 < 32) produce(s ^ 1, kt + 1);
        if (s == 0) { mbar_wait(mbA0, ph0); ph0 ^= 1; }
        else        { mbar_wait(mbA1, ph1); ph1 ^= 1; }
        const uint32_t* Xc = Xs[s];
        const uint32_t* Wc = Wp[s];
        #pragma unroll
        for (int ks = 0; ks < 2; ks++) {
            uint32_t a[2][4];
            #pragma unroll
            for (int mt = 0; mt < 2; mt++) {
                uint4 av = *(const uint4*)&Xc[(wm * 2 + mt) * 384 + lane * 12 + ks * 4];
                a[mt][0] = av.x; a[mt][1] = av.y; a[mt][2] = av.z; a[mt][3] = av.w;
            }
            #pragma unroll
            for (int nt = 0; nt < 6; nt++) {
                uint2 bv = *(const uint2*)&Wc[(((wn * 6 + nt) * 2 + ks) * 32 + lane) * 2];
                mma16(acc[0][nt], a[0], bv.x, bv.y);
                mma16(acc[1][nt], a[1], bv.x, bv.y);
            }
        }
        __syncthreads();
    }

    // epilogue: pack bf16 pairs, route by z into fragment-major tile images
    const int bb = m0 >> 11;
    const int bh = bb * H + h;
    #pragma unroll
    for (int mt = 0; mt < 2; mt++) {
        int mrow = m0 + wm * 32 + mt * 16 + g;
        int s = mrow & (S - 1);
        #pragma unroll
        for (int nt = 0; nt < 6; nt++) {
            int n = wn * 48 + nt * 8 + 2 * tq;
            int z = n >> 6;
            int dhp = (n & 63) >> 1;
            float sc = (z == 0) ? 0.125f : 1.0f;
            uint32_t u0 = f2bf2(acc[mt][nt].x * sc, acc[mt][nt].y * sc);
            uint32_t u1 = f2bf2(acc[mt][nt].z * sc, acc[mt][nt].w * sc);
            if (z == 0) {
                // Q tiles [bh][qt][5120]: rg*640 + lane'*20 + ks*4 + j
                int r = s & 127;
                int ksq = dhp >> 3, tqq = dhp & 3, half = (dhp >> 2) & 1;
                size_t tb = ((size_t)bh * 16 + (s >> 7)) * 5120
                          + (size_t)(r >> 4) * 640 + ((r & 7) * 4 + tqq) * 20
                          + ksq * 4 + 2 * half;
                g_qk[tb]     = u0;   // row r   (hi=0)
                g_qk[tb + 1] = u1;   // row r+8 (hi=1)
            } else if (z == 1) {
                // K tiles [bh][st][2048]: ((nblk*4+ks)*32+lane')*2+half
                int sc64 = s & 63;
                int ksk = dhp >> 3, tqk = dhp & 3, half = (dhp >> 2) & 1;
                size_t tb = ((size_t)bh * 32 + (s >> 6)) * 2048;
                g_kk[tb + ((((sc64 >> 3) * 4 + ksk) * 32 + (sc64 & 7) * 4 + tqk) * 2 + half)] = u0;
                int sc2 = sc64 + 8;
                g_kk[tb + ((((sc2 >> 3) * 4 + ksk) * 32 + (sc2 & 7) * 4 + tqk) * 2 + half)] = u1;
            } else {
                size_t base = ((size_t)bh * S + s) * 32 + dhp;
                g_vh[base]          = u0;
                g_vh[base + 8 * 32] = u1;
            }
        }
    }
}

// ============================================================================
// Kernel 2: flash attention — bulk-copy K/V, fragment-major tiles, register P.
// grid (S/128, B*H), block 256.
// ============================================================================
#define QTW 5120
#define KVTW 2048
#define ATTN_SMEM ((QTW + 2 * 2 * KVTW) * 4)   // 53248 bytes

__global__ __launch_bounds__(256, 2) void attn_tc()
{
    extern __shared__ __align__(16) uint32_t sm[];
    uint32_t* Qs  = sm;                       // [5120]
    uint32_t* KV0 = sm + QTW;                 // 2 x (K[2048] + V[2048])
    __shared__ __align__(8) uint64_t mb[3];

    const int bh = blockIdx.y;
    const int qt = blockIdx.x;
    const int tid = threadIdx.x;
    const int w = tid >> 5, lane = tid & 31;
    const int g = lane >> 2, tq = lane & 3;
    const int wq = w * 16;

    const uint32_t mb0 = sm2u(&mb[0]), mb1 = sm2u(&mb[1]), mbq = sm2u(&mb[2]);
    if (tid == 0) { mbar_init(mb0, 1); mbar_init(mb1, 1); mbar_init(mbq, 1); }
    FENCE_ASYNC();
    __syncthreads();

    auto produce = [&](int s, int st) {
        if (tid == 0) {
            uint32_t mba = s ? mb1 : mb0;
            mbar_expect(mba, 2 * KVTW * 4);
            uint32_t* buf = KV0 + s * 2 * KVTW;
            bulkcp(sm2u(buf), &g_kk[((size_t)bh * 32 + st) * 2048], KVTW * 4, mba);
            bulkcp(sm2u(buf + KVTW), &g_vk[((size_t)bh * 32 + st) * 2048], KVTW * 4, mba);
        }
    };

    if (tid == 0) {
        mbar_expect(mbq, QTW * 4);
        bulkcp(sm2u(Qs), &g_qk[((size_t)bh * 16 + qt) * 5120], QTW * 4, mbq);
    }
    produce(0, 0);
    mbar_wait(mbq, 0);

    float m_run[2] = { -1e30f, -1e30f };
    float l_run[2] = { 0.f, 0.f };
    float4 oacc[8];
    #pragma unroll
    for (int i = 0; i < 8; i++) oacc[i] = make_float4(0.f, 0.f, 0.f, 0.f);

    int ph0 = 0, ph1 = 0;
    for (int st = 0; st < 32; st++) {
        const int s = st & 1;
        if (st + 1 < 32) produce(s ^ 1, st + 1);
        if (s == 0) { mbar_wait(mb0, ph0); ph0 ^= 1; }
        else        { mbar_wait(mb1, ph1); ph1 ^= 1; }
        const uint32_t* Kp = KV0 + s * 2 * KVTW;
        const uint32_t* Vp = Kp + KVTW;

        // ---- scores S = Q @ K^T ----
        float4 sacc[8];
        #pragma unroll
        for (int i = 0; i < 8; i++) sacc[i] = make_float4(0.f, 0.f, 0.f, 0.f);

        #pragma unroll
        for (int ks = 0; ks < 4; ks++) {
            uint4 av = *(const uint4*)&Qs[w * 640 + lane * 20 + ks * 4];
            uint32_t a[4] = { av.x, av.y, av.z, av.w };
            #pragma unroll
            for (int nt = 0; nt < 8; nt++) {
                uint2 bk = *(const uint2*)&Kp[((nt * 4 + ks) * 32 + lane) * 2];
                mma16(sacc[nt], a, bk.x, bk.y);
            }
        }

        // ---- online softmax (rows wq+g, wq+g+8) ----
        float tm0 = -1e30f, tm1 = -1e30f;
        #pragma unroll
        for (int nt = 0; nt < 8; nt++) {
            tm0 = fmaxf(tm0, fmaxf(sacc[nt].x, sacc[nt].y));
            tm1 = fmaxf(tm1, fmaxf(sacc[nt].z, sacc[nt].w));
        }
        tm0 = fmaxf(tm0, __shfl_xor_sync(0xffffffffu, tm0, 1));
        tm0 = fmaxf(tm0, __shfl_xor_sync(0xffffffffu, tm0, 2));
        tm1 = fmaxf(tm1, __shfl_xor_sync(0xffffffffu, tm1, 1));
        tm1 = fmaxf(tm1, __shfl_xor_sync(0xffffffffu, tm1, 2));

        float mn0 = fmaxf(m_run[0], tm0);
        float mn1 = fmaxf(m_run[1], tm1);
        float al0 = __expf(m_run[0] - mn0);
        float al1 = __expf(m_run[1] - mn1);
        m_run[0] = mn0; m_run[1] = mn1;

        // P stays in registers as PV A-fragments (FA2 layout identity)
        uint32_t pa[4][4];
        float rs0 = 0.f, rs1 = 0.f;
        #pragma unroll
        for (int nt = 0; nt < 8; nt++) {
            float p0 = __expf(sacc[nt].x - mn0);
            float p1 = __expf(sacc[nt].y - mn0);
            float p2 = __expf(sacc[nt].z - mn1);
            float p3 = __expf(sacc[nt].w - mn1);
            rs0 += p0 + p1; rs1 += p2 + p3;
            int ks2 = nt >> 1;
            if ((nt & 1) == 0) {
                pa[ks2][0] = f2bf2(p0, p1);
                pa[ks2][1] = f2bf2(p2, p3);
            } else {
                pa[ks2][2] = f2bf2(p0, p1);
                pa[ks2][3] = f2bf2(p2, p3);
            }
        }
        rs0 += __shfl_xor_sync(0xffffffffu, rs0, 1);
        rs0 += __shfl_xor_sync(0xffffffffu, rs0, 2);
        rs1 += __shfl_xor_sync(0xffffffffu, rs1, 1);
        rs1 += __shfl_xor_sync(0xffffffffu, rs1, 2);
        l_run[0] = l_run[0] * al0 + rs0;
        l_run[1] = l_run[1] * al1 + rs1;
        #pragma unroll
        for (int nt = 0; nt < 8; nt++) {
            oacc[nt].x *= al0; oacc[nt].y *= al0;
            oacc[nt].z *= al1; oacc[nt].w *= al1;
        }

        // ---- PV: oacc += P @ V ----
        #pragma unroll
        for (int ks = 0; ks < 4; ks++) {
            #pragma unroll
            for (int nt = 0; nt < 8; nt++) {
                uint2 bv2 = *(const uint2*)&Vp[((nt * 4 + ks) * 32 + lane) * 2];
                mma16(oacc[nt], pa[ks], bv2.x, bv2.y);
            }
        }
        __syncthreads();
    }

    // ---- epilogue: normalize, write ctx tile images [kt][m][20] ----
    const int bb = bh >> 4, h = bh & 15;
    const float inv0 = 1.f / l_run[0];
    const float inv1 = 1.f / l_run[1];
    const int r0 = qt * 128 + wq + g;
    const size_t mrow0 = (size_t)bb * S + r0;
    #pragma unroll
    for (int nt = 0; nt < 8; nt++) {
        int dhp = nt * 4 + tq;
        int dp = h * 32 + dhp;
        size_t base = ((size_t)(dp >> 4) * M + mrow0) * 20 + (dp & 15);
        g_ctk[base]          = f2bf2(oacc[nt].x * inv0, oacc[nt].y * inv0);
        g_ctk[base + 8 * 20] = f2bf2(oacc[nt].z * inv1, oacc[nt].w * inv1);
    }
}

// ============================================================================
// Kernel 3: output projection + bias + residual (unchanged from R9).
// ============================================================================
#define PXB 20
#define POB 136
#define PRJ_XB (128 * PXB * 4)
#define PRJ_WB (16 * POB * 4)

__global__ __launch_bounds__(256, 2) void proj_tc(
    const float* __restrict__ x,
    const float* __restrict__ bo)
{
    __shared__ __align__(16) uint32_t Xs[2][128 * PXB];
    __shared__ __align__(16) uint32_t Wp[2][16 * POB];
    __shared__ __align__(8)  uint64_t mb[2];

    const int m0 = blockIdx.x * 128;
    const int nb0 = blockIdx.y;
    const int n0 = nb0 * 128;

    const int tid = threadIdx.x;
    const int w = tid >> 5, lane = tid & 31;
    const int g = lane >> 2, tq = lane & 3;
    const int wm = w >> 2, wn = w & 3;

    const uint32_t mbA0 = sm2u(&mb[0]), mbA1 = sm2u(&mb[1]);
    if (tid == 0) { mbar_init(mbA0, 1); mbar_init(mbA1, 1); }
    FENCE_ASYNC();
    __syncthreads();

    auto produce = [&](int s, int kt) {
        if (tid == 0) {
            uint32_t mba = s ? mbA1 : mbA0;
            mbar_expect(mba, PRJ_XB + PRJ_WB);
            bulkcp(sm2u(&Xs[s][0]), &g_ctk[((size_t)kt * M + m0) * 20], PRJ_XB, mba);
            bulkcp(sm2u(&Wp[s][0]),
                   &g_wok[(((size_t)nb0 * 32 + kt) * 16) * 136], PRJ_WB, mba);
        }
    };

    float4 acc[4][4];
    #pragma unroll
    for (int i = 0; i < 4; i++)
        #pragma unroll
        for (int j = 0; j < 4; j++) acc[i][j] = make_float4(0.f, 0.f, 0.f, 0.f);

    int ph0 = 0, ph1 = 0;
    produce(0, 0);

    for (int kt = 0; kt < 32; kt++) {
        const int s = kt & 1;
        if (kt + 1 < 32) produce(s ^ 1, kt + 1);
        if (s == 0) { mbar_wait(mbA0, ph0); ph0 ^= 1; }
        else        { mbar_wait(mbA1, ph1); ph1 ^= 1; }
        const uint32_t* Xc = Xs[s];
        const uint32_t* Wc = Wp[s];
        #pragma unroll
        for (int ks = 0; ks < 2; ks++) {
            const int kk = ks * 8;
            uint32_t a[4][4];
            #pragma unroll
            for (int mt = 0; mt < 4; mt++) {
                int rm = wm * 64 + mt * 16;
                a[mt][0] = Xc[(rm + g) * PXB + kk + tq];
                a[mt][1] = Xc[(rm + g + 8) * PXB + kk + tq];
                a[mt][2] = Xc[(rm + g) * PXB + kk + 4 + tq];
                a[mt][3] = Xc[(rm + g + 8) * PXB + kk + 4 + tq];
            }
            #pragma unroll
            for (int nt = 0; nt < 4; nt++) {
                int nbw = wn * 32 + nt * 8;
                uint32_t b0 = Wc[(kk + tq) * POB + nbw + g];
                uint32_t b1 = Wc[(kk + 4 + tq) * POB + nbw + g];
                #pragma unroll
                for (int mt = 0; mt < 4; mt++) mma16(acc[mt][nt], a[mt], b0, b1);
            }
        }
        __syncthreads();
    }

    #pragma unroll
    for (int mt = 0; mt < 4; mt++) {
        int m = m0 + wm * 64 + mt * 16 + g;
        #pragma unroll
        for (int nt = 0; nt < 4; nt++) {
            int col = n0 + wn * 32 + nt * 8 + 2 * tq;
            float2 b2 = *(const float2*)&bo[col];
            float2 x0 = *(const float2*)&x[(size_t)m * D + col];
            float2 x1 = *(const float2*)&x[(size_t)(m + 8) * D + col];
            *(float2*)&g_tmp[(size_t)m * D + col] =
                make_float2(acc[mt][nt].x + b2.x + x0.x, acc[mt][nt].y + b2.y + x0.y);
            *(float2*)&g_tmp[(size_t)(m + 8) * D + col] =
                make_float2(acc[mt][nt].z + b2.x + x1.x, acc[mt][nt].w + b2.y + x1.y);
        }
    }
}

// ============================================================================
// Kernel 4: LayerNorm per row.
// ============================================================================
__global__ __launch_bounds__(256) void ln_kernel(
    const float* __restrict__ gamma,
    const float* __restrict__ beta,
    float* __restrict__ out)
{
    const int row = blockIdx.x;
    const int t = threadIdx.x;
    const float4* src = (const float4*)(g_tmp + (size_t)row * D);
    float4 v = src[t];

    float s = v.x + v.y + v.z + v.w;
    float q = v.x * v.x + v.y * v.y + v.z * v.z + v.w * v.w;
    #pragma unroll
    for (int o = 16; o > 0; o >>= 1) {
        s += __shfl_xor_sync(0xffffffffu, s, o);
        q += __shfl_xor_sync(0xffffffffu, q, o);
    }
    __shared__ float sh[16];
    int w = t >> 5, lane = t & 31;
    if (lane == 0) { sh[w] = s; sh[8 + w] = q; }
    __syncthreads();
    if (t < 32) {
        s = (lane < 8) ? sh[lane] : 0.f;
        q = (lane < 8) ? sh[8 + lane] : 0.f;
        #pragma unroll
        for (int o = 4; o > 0; o >>= 1) {
            s += __shfl_xor_sync(0xffffffffu, s, o);
            q += __shfl_xor_sync(0xffffffffu, q, o);
        }
        if (lane == 0) { sh[0] = s; sh[1] = q; }
    }
    __syncthreads();
    float mu  = sh[0] * (1.f / D);
    float var = sh[1] * (1.f / D) - mu * mu;
    float rstd = rsqrtf(var + EPS);

    float4 g = ((const float4*)gamma)[t];
    float4 bb = ((const float4*)beta)[t];
    float4 o4;
    o4.x = (v.x - mu) * rstd * g.x + bb.x;
    o4.y = (v.y - mu) * rstd * g.y + bb.y;
    o4.z = (v.z - mu) * rstd * g.z + bb.z;
    o4.w = (v.w - mu) * rstd * g.w + bb.w;
    ((float4*)(out + (size_t)row * D))[t] = o4;
}

// ============================================================================
// launcher
// ============================================================================
extern "C" void kernel_launch(void* const* d_in, const int* in_sizes, int n_in,
                              void* d_out, int out_size)
{
    const float* x     = (const float*)d_in[0];
    const float* Wq    = (const float*)d_in[1];
    const float* Wk    = (const float*)d_in[2];
    const float* Wv    = (const float*)d_in[3];
    const float* Wo    = (const float*)d_in[4];
    const float* bo    = (const float*)d_in[5];
    const float* gamma = (const float*)d_in[6];
    const float* beta  = (const float*)d_in[7];
    float* out = (float*)d_out;

    cudaFuncSetAttribute(attn_tc,
                         cudaFuncAttributeMaxDynamicSharedMemorySize, ATTN_SMEM);

    cvt_x_kernel<<<(M * 512) / 256, 256>>>(x);
    cvt_wqkv_kernel<<<(H * 512 * 192) / 256, 256>>>(Wq, Wk, Wv);
    cvt_wo_kernel<<<(512 * 1024) / 256, 256>>>(Wo);
    qkv_tc<<<dim3(M / 128, H), 512>>>();
    vtr_kernel<<<(B * H * 1024 * 32) / 256, 256>>>();
    attn_tc<<<dim3(S / 128, B * H), 256, ATTN_SMEM>>>();
    proj_tc<<<dim3(M / 128, 8), 256>>>(x, bo);
    ln_kernel<<<M, 256>>>(gamma, beta, out);
}

// round 12
// speedup vs baseline: 1.4085x; 1.4085x over previous
#include <cuda_runtime.h>
#include <math.h>
#include <stdint.h>

#define B 4
#define S 2048
#define D 1024
#define H 16
#define DH 64
#define M (B * S)          // 8192
#define EPS 1e-5f

// ---------------- scratch: gmem tile images (padded SMEM layouts) ----------
__device__ uint32_t g_xk[(size_t)32 * M * 20];        // X tiles [kt][m][20]  (16 kp + 4 pad)
__device__ uint32_t g_wqk[(size_t)H * 32 * 16 * 200]; // QKV W tiles [h][kt][16][200] (192+8 pad)
__device__ uint32_t g_wok[(size_t)8 * 32 * 16 * 136]; // Wo tiles [nb][kt][16][136] (128+8 pad)
__device__ uint32_t g_qk[(size_t)B * H * 16 * 128 * 36]; // Q tiles [bh][qt][128][36], pre-scaled
__device__ uint32_t g_kk[(size_t)B * H * 32 * 32 * 72];  // K tiles [bh][st][32 dhp][72] (64 s + pad)
__device__ uint32_t g_vh[(size_t)B * H * S * 32];     // V raw [bh][s][dhp]
__device__ uint32_t g_vk[(size_t)B * H * 32 * 32 * 72];  // V tiles [bh][st][32 sp][72] (64 dh + pad)
__device__ uint32_t g_ctk[(size_t)32 * M * 20];       // ctx tiles [kt][m][20]
__device__ float    g_tmp[(size_t)B * S * D];         // proj + residual, pre-LN (fp32)

// ---------------- helpers ----------------
__device__ __forceinline__ uint32_t f2bf2(float lo, float hi) {
    uint32_t d;
    asm("cvt.rn.bf16x2.f32 %0, %1, %2;" : "=r"(d) : "f"(hi), "f"(lo));
    return d;
}
__device__ __forceinline__ uint32_t prmt(uint32_t a, uint32_t b, uint32_t s) {
    uint32_t d;
    asm("prmt.b32 %0, %1, %2, %3;" : "=r"(d) : "r"(a), "r"(b), "r"(s));
    return d;
}
__device__ __forceinline__ uint32_t sm2u(const void* p) {
    return (uint32_t)__cvta_generic_to_shared(p);
}
__device__ __forceinline__ void mbar_init(uint32_t a, uint32_t cnt) {
    asm volatile("mbarrier.init.shared.b64 [%0], %1;" :: "r"(a), "r"(cnt) : "memory");
}
__device__ __forceinline__ void mbar_expect(uint32_t a, uint32_t bytes) {
    asm volatile("mbarrier.arrive.expect_tx.shared.b64 _, [%0], %1;"
                 :: "r"(a), "r"(bytes) : "memory");
}
__device__ __forceinline__ void mbar_wait(uint32_t a, int ph) {
    asm volatile(
        "{\n\t.reg .pred P;\n\t"
        "WL%=:\n\t"
        "mbarrier.try_wait.parity.shared::cta.b64 P, [%0], %1;\n\t"
        "@P bra WD%=;\n\t"
        "bra WL%=;\n\t"
        "WD%=:\n\t}"
        :: "r"(a), "r"(ph) : "memory");
}
__device__ __forceinline__ void bulkcp(uint32_t dst, const void* src,
                                       uint32_t bytes, uint32_t mbar) {
    asm volatile(
        "cp.async.bulk.shared::cluster.global.mbarrier::complete_tx::bytes "
        "[%0], [%1], %2, [%3];"
        :: "r"(dst), "l"(src), "r"(bytes), "r"(mbar) : "memory");
}
#define FENCE_ASYNC() asm volatile("fence.proxy.async.shared::cta;" ::: "memory")

// D = A(16x16,row) * B(16x8,col) + D, bf16 in, f32 accum
__device__ __forceinline__ void mma16(float4& c, const uint32_t a[4],
                                      uint32_t b0, uint32_t b1) {
    asm volatile(
        "mma.sync.aligned.m16n8k16.row.col.f32.bf16.bf16.f32 "
        "{%0,%1,%2,%3}, {%4,%5,%6,%7}, {%8,%9}, {%0,%1,%2,%3};"
        : "+f"(c.x), "+f"(c.y), "+f"(c.z), "+f"(c.w)
        : "r"(a[0]), "r"(a[1]), "r"(a[2]), "r"(a[3]), "r"(b0), "r"(b1));
}

// ============================================================================
// Prologue packers: fp32 inputs -> bf16-pair tile images.
// ============================================================================
__global__ __launch_bounds__(256) void cvt_x_kernel(const float* __restrict__ x)
{
    int idx = blockIdx.x * 256 + threadIdx.x;       // over M*512
    int m = idx >> 9, dp = idx & 511;
    float2 v = *(const float2*)&x[(size_t)idx * 2];
    g_xk[((size_t)(dp >> 4) * M + m) * 20 + (dp & 15)] = f2bf2(v.x, v.y);
}

__global__ __launch_bounds__(256) void cvt_wqkv_kernel(
    const float* __restrict__ Wq,
    const float* __restrict__ Wk,
    const float* __restrict__ Wv)
{
    int idx = blockIdx.x * 256 + threadIdx.x;       // over H*512*192
    int n  = idx % 192;
    int kp = (idx / 192) & 511;
    int h  = idx / (192 * 512);
    int z = n >> 6, dh = n & 63;
    const float* W = (z == 0) ? Wq : (z == 1) ? Wk : Wv;
    size_t base = ((size_t)h * D + 2 * kp) * DH + dh;
    g_wqk[(((size_t)h * 32 + (kp >> 4)) * 16 + (kp & 15)) * 200 + n] =
        f2bf2(W[base], W[base + DH]);
}

__global__ __launch_bounds__(256) void cvt_wo_kernel(const float* __restrict__ Wo)
{
    int idx = blockIdx.x * 256 + threadIdx.x;       // over 512*1024
    int n = idx & 1023;
    int kp = idx >> 10;
    g_wok[(((size_t)(n >> 7) * 32 + (kp >> 4)) * 16 + (kp & 15)) * 136 + (n & 127)] =
        f2bf2(Wo[(size_t)(2 * kp) * 1024 + n], Wo[(size_t)(2 * kp + 1) * 1024 + n]);
}

// V transpose: [bh][s][dhp] -> tiles [bh][st][sp][72]
__global__ __launch_bounds__(256) void vtr_kernel()
{
    int idx = blockIdx.x * 256 + threadIdx.x;       // over B*H*1024*32
    int dp = idx & 31;
    int sp = (idx >> 5) & 1023;
    int bh = idx >> 15;
    uint32_t va = g_vh[((size_t)bh * S + 2 * sp) * 32 + dp];
    uint32_t vb = g_vh[((size_t)bh * S + 2 * sp + 1) * 32 + dp];
    *(uint2*)&g_vk[(((size_t)bh * 32 + (sp >> 5)) * 32 + (sp & 31)) * 72 + 2 * dp] =
        make_uint2(prmt(va, vb, 0x5410), prmt(va, vb, 0x7632));
}

// ============================================================================
// Kernel 1: QKV projection, z-folded, bulk-copy pipelined (R9, unchanged).
// grid (M/128, H), block 512, 16 warps 4m x 4n, warp tile 32x48.
// ============================================================================
#define XSB 20
#define WPB 200
#define QKV_XB (128 * XSB * 4)    // 10240
#define QKV_WB (16 * WPB * 4)     // 12800

__global__ __launch_bounds__(512, 2) void qkv_tc()
{
    __shared__ __align__(16) uint32_t Xs[2][128 * XSB];
    __shared__ __align__(16) uint32_t Wp[2][16 * WPB];
    __shared__ __align__(8)  uint64_t mb[2];

    const int m0 = blockIdx.x * 128;
    const int h  = blockIdx.y;

    const int tid = threadIdx.x;
    const int w = tid >> 5, lane = tid & 31;
    const int g = lane >> 2, tq = lane & 3;
    const int wm = w >> 2, wn = w & 3;

    const uint32_t mbA0 = sm2u(&mb[0]), mbA1 = sm2u(&mb[1]);
    if (tid == 0) { mbar_init(mbA0, 1); mbar_init(mbA1, 1); }
    FENCE_ASYNC();
    __syncthreads();

    auto produce = [&](int s, int kt) {
        if (tid == 0) {
            uint32_t mba = s ? mbA1 : mbA0;
            mbar_expect(mba, QKV_XB + QKV_WB);
            bulkcp(sm2u(&Xs[s][0]), &g_xk[((size_t)kt * M + m0) * 20], QKV_XB, mba);
            bulkcp(sm2u(&Wp[s][0]), &g_wqk[(((size_t)h * 32 + kt) * 16) * 200], QKV_WB, mba);
        }
    };

    float4 acc[2][6];
    #pragma unroll
    for (int i = 0; i < 2; i++)
        #pragma unroll
        for (int j = 0; j < 6; j++) acc[i][j] = make_float4(0.f, 0.f, 0.f, 0.f);

    int ph0 = 0, ph1 = 0;
    produce(0, 0);

    for (int kt = 0; kt < 32; kt++) {
        const int s = kt & 1;
        if (kt + 1 < 32) produce(s ^ 1, kt + 1);
        if (s == 0) { mbar_wait(mbA0, ph0); ph0 ^= 1; }
        else        { mbar_wait(mbA1, ph1); ph1 ^= 1; }
        const uint32_t* Xc = Xs[s];
        const uint32_t* Wc = Wp[s];
        #pragma unroll
        for (int ks = 0; ks < 2; ks++) {
            const int kk = ks * 8;
            uint32_t a[2][4];
            #pragma unroll
            for (int mt = 0; mt < 2; mt++) {
                int rm = wm * 32 + mt * 16;
                a[mt][0] = Xc[(rm + g) * XSB + kk + tq];
                a[mt][1] = Xc[(rm + g + 8) * XSB + kk + tq];
                a[mt][2] = Xc[(rm + g) * XSB + kk + 4 + tq];
                a[mt][3] = Xc[(rm + g + 8) * XSB + kk + 4 + tq];
            }
            #pragma unroll
            for (int nt = 0; nt < 6; nt++) {
                int nb = wn * 48 + nt * 8;
                uint32_t b0 = Wc[(kk + tq) * WPB + nb + g];
                uint32_t b1 = Wc[(kk + 4 + tq) * WPB + nb + g];
                mma16(acc[0][nt], a[0], b0, b1);
                mma16(acc[1][nt], a[1], b0, b1);
            }
        }
        __syncthreads();
    }

    // epilogue: pack bf16 pairs, route by z into tile images
    const int bb = m0 >> 11;
    const int bh = bb * H + h;
    #pragma unroll
    for (int mt = 0; mt < 2; mt++) {
        int mrow = m0 + wm * 32 + mt * 16 + g;
        int s = mrow & (S - 1);
        #pragma unroll
        for (int nt = 0; nt < 6; nt++) {
            int n = wn * 48 + nt * 8 + 2 * tq;
            int z = n >> 6, dhp = (n & 63) >> 1;
            float sc = (z == 0) ? 0.125f : 1.0f;
            uint32_t u0 = f2bf2(acc[mt][nt].x * sc, acc[mt][nt].y * sc);
            uint32_t u1 = f2bf2(acc[mt][nt].z * sc, acc[mt][nt].w * sc);
            if (z == 0) {        // Q tiles [bh][qt][128][36]
                size_t base = (((size_t)bh * 16 + (s >> 7)) * 128 + (s & 127)) * 36 + dhp;
                g_qk[base]          = u0;
                g_qk[base + 8 * 36] = u1;
            } else if (z == 1) { // K tiles [bh][st][dhp][72]
                size_t base = (((size_t)bh * 32 + (s >> 6)) * 32 + dhp) * 72 + (s & 63);
                g_kk[base]     = u0;
                g_kk[base + 8] = u1;
            } else {             // V raw [bh][s][dhp]
                size_t base = ((size_t)bh * S + s) * 32 + dhp;
                g_vh[base]          = u0;
                g_vh[base + 8 * 32] = u1;
            }
        }
    }
}

// ============================================================================
// Kernel 2: flash attention, bulk-copy pipelined K/V, REGISTER-RESIDENT P.
// grid (S/128, B*H), block 256.
// ============================================================================
#define QSB 36
#define KVB 72
#define KVW (32 * KVB * 2)                 // words per KV buffer (4608)
#define KVBYTES (32 * KVB * 4)             // 9216 per operand
#define ATTN_SMEM ((128 * QSB + 2 * KVW) * 4)

__global__ __launch_bounds__(256, 2) void attn_tc()
{
    extern __shared__ __align__(16) uint32_t sm[];
    uint32_t* Qs  = sm;                      // [128][36]
    uint32_t* KV0 = sm + 128 * QSB;          // 2 x (K[32][72] + V[32][72])
    __shared__ __align__(8) uint64_t mb[3];  // kv0, kv1, q

    const int bh = blockIdx.y;
    const int qt = blockIdx.x;
    const int tid = threadIdx.x;
    const int w = tid >> 5, lane = tid & 31;
    const int g = lane >> 2, tq = lane & 3;
    const int wq = w * 16;

    const uint32_t mb0 = sm2u(&mb[0]), mb1 = sm2u(&mb[1]), mbq = sm2u(&mb[2]);
    if (tid == 0) { mbar_init(mb0, 1); mbar_init(mb1, 1); mbar_init(mbq, 1); }
    FENCE_ASYNC();
    __syncthreads();

    auto produce = [&](int s, int st) {
        if (tid == 0) {
            uint32_t mba = s ? mb1 : mb0;
            mbar_expect(mba, 2 * KVBYTES);
            uint32_t* buf = KV0 + s * KVW;
            bulkcp(sm2u(buf), &g_kk[(((size_t)bh * 32 + st) * 32) * 72], KVBYTES, mba);
            bulkcp(sm2u(buf + 32 * KVB),
                   &g_vk[(((size_t)bh * 32 + st) * 32) * 72], KVBYTES, mba);
        }
    };

    if (tid == 0) {
        mbar_expect(mbq, 128 * QSB * 4);
        bulkcp(sm2u(Qs), &g_qk[(((size_t)bh * 16 + qt) * 128) * 36], 128 * QSB * 4, mbq);
    }
    produce(0, 0);
    mbar_wait(mbq, 0);

    float m_run[2] = { -1e30f, -1e30f };
    float l_run[2] = { 0.f, 0.f };
    float4 oacc[8];
    #pragma unroll
    for (int i = 0; i < 8; i++) oacc[i] = make_float4(0.f, 0.f, 0.f, 0.f);

    int ph0 = 0, ph1 = 0;
    for (int st = 0; st < 32; st++) {
        const int s = st & 1;
        if (st + 1 < 32) produce(s ^ 1, st + 1);
        if (s == 0) { mbar_wait(mb0, ph0); ph0 ^= 1; }
        else        { mbar_wait(mb1, ph1); ph1 ^= 1; }
        const uint32_t* Kp = KV0 + s * KVW;
        const uint32_t* Vp = Kp + 32 * KVB;

        // ---- scores S = Q @ K^T ----
        float4 sacc[8];
        #pragma unroll
        for (int i = 0; i < 8; i++) sacc[i] = make_float4(0.f, 0.f, 0.f, 0.f);

        #pragma unroll
        for (int ks = 0; ks < 4; ks++) {
            const int kp0 = ks * 8;
            uint32_t a[4];
            a[0] = Qs[(wq + g) * QSB + kp0 + tq];
            a[1] = Qs[(wq + g + 8) * QSB + kp0 + tq];
            a[2] = Qs[(wq + g) * QSB + kp0 + 4 + tq];
            a[3] = Qs[(wq + g + 8) * QSB + kp0 + 4 + tq];
            #pragma unroll
            for (int nt = 0; nt < 8; nt++) {
                uint32_t b0 = Kp[(kp0 + tq) * KVB + nt * 8 + g];
                uint32_t b1 = Kp[(kp0 + 4 + tq) * KVB + nt * 8 + g];
                mma16(sacc[nt], a, b0, b1);
            }
        }

        // ---- online softmax (rows wq+g, wq+g+8) ----
        float tm0 = -1e30f, tm1 = -1e30f;
        #pragma unroll
        for (int nt = 0; nt < 8; nt++) {
            tm0 = fmaxf(tm0, fmaxf(sacc[nt].x, sacc[nt].y));
            tm1 = fmaxf(tm1, fmaxf(sacc[nt].z, sacc[nt].w));
        }
        tm0 = fmaxf(tm0, __shfl_xor_sync(0xffffffffu, tm0, 1));
        tm0 = fmaxf(tm0, __shfl_xor_sync(0xffffffffu, tm0, 2));
        tm1 = fmaxf(tm1, __shfl_xor_sync(0xffffffffu, tm1, 1));
        tm1 = fmaxf(tm1, __shfl_xor_sync(0xffffffffu, tm1, 2));

        float mn0 = fmaxf(m_run[0], tm0);
        float mn1 = fmaxf(m_run[1], tm1);
        float al0 = __expf(m_run[0] - mn0);
        float al1 = __expf(m_run[1] - mn1);
        m_run[0] = mn0; m_run[1] = mn1;

        // P stays in registers as PV A-fragments (FA2 layout identity):
        // pa[ks][0] = P[row g][cols 16ks+2tq..+1], pa[ks][1] = row g+8 same cols,
        // pa[ks][2] = row g cols +8, pa[ks][3] = row g+8 cols +8.
        uint32_t pa[4][4];
        float rs0 = 0.f, rs1 = 0.f;
        #pragma unroll
        for (int nt = 0; nt < 8; nt++) {
            float p0 = __expf(sacc[nt].x - mn0);
            float p1 = __expf(sacc[nt].y - mn0);
            float p2 = __expf(sacc[nt].z - mn1);
            float p3 = __expf(sacc[nt].w - mn1);
            rs0 += p0 + p1; rs1 += p2 + p3;
            int ks2 = nt >> 1;
            if ((nt & 1) == 0) {
                pa[ks2][0] = f2bf2(p0, p1);
                pa[ks2][1] = f2bf2(p2, p3);
            } else {
                pa[ks2][2] = f2bf2(p0, p1);
                pa[ks2][3] = f2bf2(p2, p3);
            }
        }
        rs0 += __shfl_xor_sync(0xffffffffu, rs0, 1);
        rs0 += __shfl_xor_sync(0xffffffffu, rs0, 2);
        rs1 += __shfl_xor_sync(0xffffffffu, rs1, 1);
        rs1 += __shfl_xor_sync(0xffffffffu, rs1, 2);
        l_run[0] = l_run[0] * al0 + rs0;
        l_run[1] = l_run[1] * al1 + rs1;
        #pragma unroll
        for (int nt = 0; nt < 8; nt++) {
            oacc[nt].x *= al0; oacc[nt].y *= al0;
            oacc[nt].z *= al1; oacc[nt].w *= al1;
        }

        // ---- PV: oacc += P @ V  (A from registers) ----
        #pragma unroll
        for (int ks = 0; ks < 4; ks++) {
            const int kp0 = ks * 8;
            #pragma unroll
            for (int nt = 0; nt < 8; nt++) {
                uint32_t b0 = Vp[(kp0 + tq) * KVB + nt * 8 + g];
                uint32_t b1 = Vp[(kp0 + 4 + tq) * KVB + nt * 8 + g];
                mma16(oacc[nt], pa[ks], b0, b1);
            }
        }
        __syncthreads();
    }

    // ---- epilogue: normalize, write ctx tile images [kt][m][20] ----
    const int bb = bh >> 4, h = bh & 15;
    const float inv0 = 1.f / l_run[0];
    const float inv1 = 1.f / l_run[1];
    const int r0 = qt * 128 + wq + g;
    const size_t mrow0 = (size_t)bb * S + r0;
    #pragma unroll
    for (int nt = 0; nt < 8; nt++) {
        int dhp = nt * 4 + tq;
        int dp = h * 32 + dhp;
        size_t base = ((size_t)(dp >> 4) * M + mrow0) * 20 + (dp & 15);
        g_ctk[base]          = f2bf2(oacc[nt].x * inv0, oacc[nt].y * inv0);
        g_ctk[base + 8 * 20] = f2bf2(oacc[nt].z * inv1, oacc[nt].w * inv1);
    }
}

// ============================================================================
// Kernel 3: output projection + bias + residual (R9, unchanged).
// ============================================================================
#define PXB 20
#define POB 136
#define PRJ_XB (128 * PXB * 4)    // 10240
#define PRJ_WB (16 * POB * 4)     // 8704

__global__ __launch_bounds__(256, 2) void proj_tc(
    const float* __restrict__ x,
    const float* __restrict__ bo)
{
    __shared__ __align__(16) uint32_t Xs[2][128 * PXB];
    __shared__ __align__(16) uint32_t Wp[2][16 * POB];
    __shared__ __align__(8)  uint64_t mb[2];

    const int m0 = blockIdx.x * 128;
    const int nb0 = blockIdx.y;              // 128-col block
    const int n0 = nb0 * 128;

    const int tid = threadIdx.x;
    const int w = tid >> 5, lane = tid & 31;
    const int g = lane >> 2, tq = lane & 3;
    const int wm = w >> 2, wn = w & 3;

    const uint32_t mbA0 = sm2u(&mb[0]), mbA1 = sm2u(&mb[1]);
    if (tid == 0) { mbar_init(mbA0, 1); mbar_init(mbA1, 1); }
    FENCE_ASYNC();
    __syncthreads();

    auto produce = [&](int s, int kt) {
        if (tid == 0) {
            uint32_t mba = s ? mbA1 : mbA0;
            mbar_expect(mba, PRJ_XB + PRJ_WB);
            bulkcp(sm2u(&Xs[s][0]), &g_ctk[((size_t)kt * M + m0) * 20], PRJ_XB, mba);
            bulkcp(sm2u(&Wp[s][0]),
                   &g_wok[(((size_t)nb0 * 32 + kt) * 16) * 136], PRJ_WB, mba);
        }
    };

    float4 acc[4][4];
    #pragma unroll
    for (int i = 0; i < 4; i++)
        #pragma unroll
        for (int j = 0; j < 4; j++) acc[i][j] = make_float4(0.f, 0.f, 0.f, 0.f);

    int ph0 = 0, ph1 = 0;
    produce(0, 0);

    for (int kt = 0; kt < 32; kt++) {
        const int s = kt & 1;
        if (kt + 1 < 32) produce(s ^ 1, kt + 1);
        if (s == 0) { mbar_wait(mbA0, ph0); ph0 ^= 1; }
        else        { mbar_wait(mbA1, ph1); ph1 ^= 1; }
        const uint32_t* Xc = Xs[s];
        const uint32_t* Wc = Wp[s];
        #pragma unroll
        for (int ks = 0; ks < 2; ks++) {
            const int kk = ks * 8;
            uint32_t a[4][4];
            #pragma unroll
            for (int mt = 0; mt < 4; mt++) {
                int rm = wm * 64 + mt * 16;
                a[mt][0] = Xc[(rm + g) * PXB + kk + tq];
                a[mt][1] = Xc[(rm + g + 8) * PXB + kk + tq];
                a[mt][2] = Xc[(rm + g) * PXB + kk + 4 + tq];
                a[mt][3] = Xc[(rm + g + 8) * PXB + kk + 4 + tq];
            }
            #pragma unroll
            for (int nt = 0; nt < 4; nt++) {
                int nbw = wn * 32 + nt * 8;
                uint32_t b0 = Wc[(kk + tq) * POB + nbw + g];
                uint32_t b1 = Wc[(kk + 4 + tq) * POB + nbw + g];
                #pragma unroll
                for (int mt = 0; mt < 4; mt++) mma16(acc[mt][nt], a[mt], b0, b1);
            }
        }
        __syncthreads();
    }

    #pragma unroll
    for (int mt = 0; mt < 4; mt++) {
        int m = m0 + wm * 64 + mt * 16 + g;
        #pragma unroll
        for (int nt = 0; nt < 4; nt++) {
            int col = n0 + wn * 32 + nt * 8 + 2 * tq;
            float2 b2 = *(const float2*)&bo[col];
            float2 x0 = *(const float2*)&x[(size_t)m * D + col];
            float2 x1 = *(const float2*)&x[(size_t)(m + 8) * D + col];
            *(float2*)&g_tmp[(size_t)m * D + col] =
                make_float2(acc[mt][nt].x + b2.x + x0.x, acc[mt][nt].y + b2.y + x0.y);
            *(float2*)&g_tmp[(size_t)(m + 8) * D + col] =
                make_float2(acc[mt][nt].z + b2.x + x1.x, acc[mt][nt].w + b2.y + x1.y);
        }
    }
}

// ============================================================================
// Kernel 4: LayerNorm per row.  grid M, block 256 (4 floats / thread).
// ============================================================================
__global__ __launch_bounds__(256) void ln_kernel(
    const float* __restrict__ gamma,
    const float* __restrict__ beta,
    float* __restrict__ out)
{
    const int row = blockIdx.x;
    const int t = threadIdx.x;
    const float4* src = (const float4*)(g_tmp + (size_t)row * D);
    float4 v = src[t];

    float s = v.x + v.y + v.z + v.w;
    float q = v.x * v.x + v.y * v.y + v.z * v.z + v.w * v.w;
    #pragma unroll
    for (int o = 16; o > 0; o >>= 1) {
        s += __shfl_xor_sync(0xffffffffu, s, o);
        q += __shfl_xor_sync(0xffffffffu, q, o);
    }
    __shared__ float sh[16];
    int w = t >> 5, lane = t & 31;
    if (lane == 0) { sh[w] = s; sh[8 + w] = q; }
    __syncthreads();
    if (t < 32) {
        s = (lane < 8) ? sh[lane] : 0.f;
        q = (lane < 8) ? sh[8 + lane] : 0.f;
        #pragma unroll
        for (int o = 4; o > 0; o >>= 1) {
            s += __shfl_xor_sync(0xffffffffu, s, o);
            q += __shfl_xor_sync(0xffffffffu, q, o);
        }
        if (lane == 0) { sh[0] = s; sh[1] = q; }
    }
    __syncthreads();
    float mu  = sh[0] * (1.f / D);
    float var = sh[1] * (1.f / D) - mu * mu;
    float rstd = rsqrtf(var + EPS);

    float4 g = ((const float4*)gamma)[t];
    float4 bb = ((const float4*)beta)[t];
    float4 o4;
    o4.x = (v.x - mu) * rstd * g.x + bb.x;
    o4.y = (v.y - mu) * rstd * g.y + bb.y;
    o4.z = (v.z - mu) * rstd * g.z + bb.z;
    o4.w = (v.w - mu) * rstd * g.w + bb.w;
    ((float4*)(out + (size_t)row * D))[t] = o4;
}

// ============================================================================
// launcher
// ============================================================================
extern "C" void kernel_launch(void* const* d_in, const int* in_sizes, int n_in,
                              void* d_out, int out_size)
{
    const float* x     = (const float*)d_in[0];
    const float* Wq    = (const float*)d_in[1];
    const float* Wk    = (const float*)d_in[2];
    const float* Wv    = (const float*)d_in[3];
    const float* Wo    = (const float*)d_in[4];
    const float* bo    = (const float*)d_in[5];
    const float* gamma = (const float*)d_in[6];
    const float* beta  = (const float*)d_in[7];
    float* out = (float*)d_out;

    cudaFuncSetAttribute(attn_tc,
                         cudaFuncAttributeMaxDynamicSharedMemorySize, ATTN_SMEM);

    cvt_x_kernel<<<(M * 512) / 256, 256>>>(x);
    cvt_wqkv_kernel<<<(H * 512 * 192) / 256, 256>>>(Wq, Wk, Wv);
    cvt_wo_kernel<<<(512 * 1024) / 256, 256>>>(Wo);
    qkv_tc<<<dim3(M / 128, H), 512>>>();
    vtr_kernel<<<(B * H * 1024 * 32) / 256, 256>>>();
    attn_tc<<<dim3(S / 128, B * H), 256, ATTN_SMEM>>>();
    proj_tc<<<dim3(M / 128, 8), 256>>>(x, bo);
    ln_kernel<<<M, 256>>>(gamma, beta, out);
}

// round 13
// speedup vs baseline: 1.5988x; 1.1351x over previous
#include <cuda_runtime.h>
#include <math.h>
#include <stdint.h>

#define B 4
#define S 2048
#define D 1024
#define H 16
#define DH 64
#define M (B * S)          // 8192
#define EPS 1e-5f

// ---------------- scratch: gmem tile images (padded SMEM layouts) ----------
__device__ uint32_t g_xk[(size_t)32 * M * 20];        // X tiles [kt][m][20]  (16 kp + 4 pad)
__device__ uint32_t g_wqk[(size_t)H * 32 * 16 * 200]; // QKV W tiles [h][kt][16][200] (192+8 pad)
__device__ uint32_t g_wok[(size_t)8 * 32 * 16 * 136]; // Wo tiles [nb][kt][16][136] (128+8 pad)
__device__ uint32_t g_qk[(size_t)B * H * 16 * 128 * 36]; // Q tiles [bh][qt][128][36], pre-scaled
__device__ uint32_t g_kk[(size_t)B * H * 32 * 32 * 72];  // K tiles [bh][st][32 dhp][72] (64 s + pad)
__device__ uint32_t g_vh[(size_t)B * H * S * 32];     // V raw [bh][s][dhp]
__device__ uint32_t g_vk[(size_t)B * H * 32 * 32 * 72];  // V tiles [bh][st][32 sp][72] (64 dh + pad)
__device__ uint32_t g_ctk[(size_t)32 * M * 20];       // ctx tiles [kt][m][20]
__device__ float    g_tmp[(size_t)B * S * D];         // proj + residual, pre-LN (fp32)

// ---------------- helpers ----------------
__device__ __forceinline__ uint32_t f2bf2(float lo, float hi) {
    uint32_t d;
    asm("cvt.rn.bf16x2.f32 %0, %1, %2;" : "=r"(d) : "f"(hi), "f"(lo));
    return d;
}
__device__ __forceinline__ uint32_t prmt(uint32_t a, uint32_t b, uint32_t s) {
    uint32_t d;
    asm("prmt.b32 %0, %1, %2, %3;" : "=r"(d) : "r"(a), "r"(b), "r"(s));
    return d;
}
__device__ __forceinline__ uint32_t sm2u(const void* p) {
    return (uint32_t)__cvta_generic_to_shared(p);
}
__device__ __forceinline__ void mbar_init(uint32_t a, uint32_t cnt) {
    asm volatile("mbarrier.init.shared.b64 [%0], %1;" :: "r"(a), "r"(cnt) : "memory");
}
__device__ __forceinline__ void mbar_expect(uint32_t a, uint32_t bytes) {
    asm volatile("mbarrier.arrive.expect_tx.shared.b64 _, [%0], %1;"
                 :: "r"(a), "r"(bytes) : "memory");
}
__device__ __forceinline__ void mbar_wait(uint32_t a, int ph) {
    asm volatile(
        "{\n\t.reg .pred P;\n\t"
        "WL%=:\n\t"
        "mbarrier.try_wait.parity.shared::cta.b64 P, [%0], %1;\n\t"
        "@P bra WD%=;\n\t"
        "bra WL%=;\n\t"
        "WD%=:\n\t}"
        :: "r"(a), "r"(ph) : "memory");
}
__device__ __forceinline__ void bulkcp(uint32_t dst, const void* src,
                                       uint32_t bytes, uint32_t mbar) {
    asm volatile(
        "cp.async.bulk.shared::cluster.global.mbarrier::complete_tx::bytes "
        "[%0], [%1], %2, [%3];"
        :: "r"(dst), "l"(src), "r"(bytes), "r"(mbar) : "memory");
}
#define FENCE_ASYNC() asm volatile("fence.proxy.async.shared::cta;" ::: "memory")

// ldmatrix.x4: loads a full 16x16 bf16 A-fragment (4 regs) in one instruction.
__device__ __forceinline__ void ldsm4(uint32_t a[4], uint32_t addr) {
    asm volatile(
        "ldmatrix.sync.aligned.m8n8.x4.shared.b16 {%0,%1,%2,%3}, [%4];"
        : "=r"(a[0]), "=r"(a[1]), "=r"(a[2]), "=r"(a[3]) : "r"(addr));
}

// D = A(16x16,row) * B(16x8,col) + D, bf16 in, f32 accum
__device__ __forceinline__ void mma16(float4& c, const uint32_t a[4],
                                      uint32_t b0, uint32_t b1) {
    asm volatile(
        "mma.sync.aligned.m16n8k16.row.col.f32.bf16.bf16.f32 "
        "{%0,%1,%2,%3}, {%4,%5,%6,%7}, {%8,%9}, {%0,%1,%2,%3};"
        : "+f"(c.x), "+f"(c.y), "+f"(c.z), "+f"(c.w)
        : "r"(a[0]), "r"(a[1]), "r"(a[2]), "r"(a[3]), "r"(b0), "r"(b1));
}

// ============================================================================
// Prologue packers: fp32 inputs -> bf16-pair tile images.
// ============================================================================
__global__ __launch_bounds__(256) void cvt_x_kernel(const float* __restrict__ x)
{
    int idx = blockIdx.x * 256 + threadIdx.x;       // over M*512
    int m = idx >> 9, dp = idx & 511;
    float2 v = *(const float2*)&x[(size_t)idx * 2];
    g_xk[((size_t)(dp >> 4) * M + m) * 20 + (dp & 15)] = f2bf2(v.x, v.y);
}

__global__ __launch_bounds__(256) void cvt_wqkv_kernel(
    const float* __restrict__ Wq,
    const float* __restrict__ Wk,
    const float* __restrict__ Wv)
{
    int idx = blockIdx.x * 256 + threadIdx.x;       // over H*512*192
    int n  = idx % 192;
    int kp = (idx / 192) & 511;
    int h  = idx / (192 * 512);
    int z = n >> 6, dh = n & 63;
    const float* W = (z == 0) ? Wq : (z == 1) ? Wk : Wv;
    size_t base = ((size_t)h * D + 2 * kp) * DH + dh;
    g_wqk[(((size_t)h * 32 + (kp >> 4)) * 16 + (kp & 15)) * 200 + n] =
        f2bf2(W[base], W[base + DH]);
}

__global__ __launch_bounds__(256) void cvt_wo_kernel(const float* __restrict__ Wo)
{
    int idx = blockIdx.x * 256 + threadIdx.x;       // over 512*1024
    int n = idx & 1023;
    int kp = idx >> 10;
    g_wok[(((size_t)(n >> 7) * 32 + (kp >> 4)) * 16 + (kp & 15)) * 136 + (n & 127)] =
        f2bf2(Wo[(size_t)(2 * kp) * 1024 + n], Wo[(size_t)(2 * kp + 1) * 1024 + n]);
}

// V transpose: [bh][s][dhp] -> tiles [bh][st][sp][72]
__global__ __launch_bounds__(256) void vtr_kernel()
{
    int idx = blockIdx.x * 256 + threadIdx.x;       // over B*H*1024*32
    int dp = idx & 31;
    int sp = (idx >> 5) & 1023;
    int bh = idx >> 15;
    uint32_t va = g_vh[((size_t)bh * S + 2 * sp) * 32 + dp];
    uint32_t vb = g_vh[((size_t)bh * S + 2 * sp + 1) * 32 + dp];
    *(uint2*)&g_vk[(((size_t)bh * 32 + (sp >> 5)) * 32 + (sp & 31)) * 72 + 2 * dp] =
        make_uint2(prmt(va, vb, 0x5410), prmt(va, vb, 0x7632));
}

// ============================================================================
// Kernel 1: QKV projection, z-folded, bulk-copy pipelined, LDSM A-frags.
// grid (M/128, H), block 512, 16 warps 4m x 4n, warp tile 32x48.
// ============================================================================
#define XSB 20
#define WPB 200
#define QKV_XB (128 * XSB * 4)    // 10240
#define QKV_WB (16 * WPB * 4)     // 12800

__global__ __launch_bounds__(512, 2) void qkv_tc()
{
    __shared__ __align__(16) uint32_t Xs[2][128 * XSB];
    __shared__ __align__(16) uint32_t Wp[2][16 * WPB];
    __shared__ __align__(8)  uint64_t mb[2];

    const int m0 = blockIdx.x * 128;
    const int h  = blockIdx.y;

    const int tid = threadIdx.x;
    const int w = tid >> 5, lane = tid & 31;
    const int g = lane >> 2, tq = lane & 3;
    const int wm = w >> 2, wn = w & 3;

    // LDSM per-lane address offset: matrix j = lane>>3 (j0=row+8, j1=khalf+4)
    const int li = lane & 7, j01 = (lane >> 3) & 1, jhi = lane >> 4;
    const uint32_t aoff = ((j01 * 8 + li) * XSB + jhi * 4) * 4;
    const uint32_t xsh[2] = { sm2u(&Xs[0][0]), sm2u(&Xs[1][0]) };

    const uint32_t mbA0 = sm2u(&mb[0]), mbA1 = sm2u(&mb[1]);
    if (tid == 0) { mbar_init(mbA0, 1); mbar_init(mbA1, 1); }
    FENCE_ASYNC();
    __syncthreads();

    auto produce = [&](int s, int kt) {
        if (tid == 0) {
            uint32_t mba = s ? mbA1 : mbA0;
            mbar_expect(mba, QKV_XB + QKV_WB);
            bulkcp(sm2u(&Xs[s][0]), &g_xk[((size_t)kt * M + m0) * 20], QKV_XB, mba);
            bulkcp(sm2u(&Wp[s][0]), &g_wqk[(((size_t)h * 32 + kt) * 16) * 200], QKV_WB, mba);
        }
    };

    float4 acc[2][6];
    #pragma unroll
    for (int i = 0; i < 2; i++)
        #pragma unroll
        for (int j = 0; j < 6; j++) acc[i][j] = make_float4(0.f, 0.f, 0.f, 0.f);

    int ph0 = 0, ph1 = 0;
    produce(0, 0);

    for (int kt = 0; kt < 32; kt++) {
        const int s = kt & 1;
        if (kt + 1 < 32) produce(s ^ 1, kt + 1);
        if (s == 0) { mbar_wait(mbA0, ph0); ph0 ^= 1; }
        else        { mbar_wait(mbA1, ph1); ph1 ^= 1; }
        const uint32_t* Wc = Wp[s];
        const uint32_t xb = xsh[s];
        #pragma unroll
        for (int ks = 0; ks < 2; ks++) {
            const int kk = ks * 8;
            uint32_t a[2][4];
            #pragma unroll
            for (int mt = 0; mt < 2; mt++) {
                int rm = wm * 32 + mt * 16;
                ldsm4(a[mt], xb + (rm * XSB + kk) * 4 + aoff);
            }
            #pragma unroll
            for (int nt = 0; nt < 6; nt++) {
                int nb = wn * 48 + nt * 8;
                uint32_t b0 = Wc[(kk + tq) * WPB + nb + g];
                uint32_t b1 = Wc[(kk + 4 + tq) * WPB + nb + g];
                mma16(acc[0][nt], a[0], b0, b1);
                mma16(acc[1][nt], a[1], b0, b1);
            }
        }
        __syncthreads();
    }

    // epilogue: pack bf16 pairs, route by z into tile images
    const int bb = m0 >> 11;
    const int bh = bb * H + h;
    #pragma unroll
    for (int mt = 0; mt < 2; mt++) {
        int mrow = m0 + wm * 32 + mt * 16 + g;
        int s = mrow & (S - 1);
        #pragma unroll
        for (int nt = 0; nt < 6; nt++) {
            int n = wn * 48 + nt * 8 + 2 * tq;
            int z = n >> 6, dhp = (n & 63) >> 1;
            float sc = (z == 0) ? 0.125f : 1.0f;
            uint32_t u0 = f2bf2(acc[mt][nt].x * sc, acc[mt][nt].y * sc);
            uint32_t u1 = f2bf2(acc[mt][nt].z * sc, acc[mt][nt].w * sc);
            if (z == 0) {        // Q tiles [bh][qt][128][36]
                size_t base = (((size_t)bh * 16 + (s >> 7)) * 128 + (s & 127)) * 36 + dhp;
                g_qk[base]          = u0;
                g_qk[base + 8 * 36] = u1;
            } else if (z == 1) { // K tiles [bh][st][dhp][72]
                size_t base = (((size_t)bh * 32 + (s >> 6)) * 32 + dhp) * 72 + (s & 63);
                g_kk[base]     = u0;
                g_kk[base + 8] = u1;
            } else {             // V raw [bh][s][dhp]
                size_t base = ((size_t)bh * S + s) * 32 + dhp;
                g_vh[base]          = u0;
                g_vh[base + 8 * 32] = u1;
            }
        }
    }
}

// ============================================================================
// Kernel 2: flash attention, bulk-copy K/V, register P, LDSM Q-frags.
// grid (S/128, B*H), block 256.
// ============================================================================
#define QSB 36
#define KVB 72
#define KVW (32 * KVB * 2)                 // words per KV buffer (4608)
#define KVBYTES (32 * KVB * 4)             // 9216 per operand
#define ATTN_SMEM ((128 * QSB + 2 * KVW) * 4)

__global__ __launch_bounds__(256, 2) void attn_tc()
{
    extern __shared__ __align__(16) uint32_t sm[];
    uint32_t* Qs  = sm;                      // [128][36]
    uint32_t* KV0 = sm + 128 * QSB;          // 2 x (K[32][72] + V[32][72])
    __shared__ __align__(8) uint64_t mb[3];  // kv0, kv1, q

    const int bh = blockIdx.y;
    const int qt = blockIdx.x;
    const int tid = threadIdx.x;
    const int w = tid >> 5, lane = tid & 31;
    const int g = lane >> 2, tq = lane & 3;
    const int wq = w * 16;

    const int li = lane & 7, j01 = (lane >> 3) & 1, jhi = lane >> 4;
    const uint32_t qoff = ((j01 * 8 + li) * QSB + jhi * 4) * 4;
    const uint32_t qsh = sm2u(Qs);

    const uint32_t mb0 = sm2u(&mb[0]), mb1 = sm2u(&mb[1]), mbq = sm2u(&mb[2]);
    if (tid == 0) { mbar_init(mb0, 1); mbar_init(mb1, 1); mbar_init(mbq, 1); }
    FENCE_ASYNC();
    __syncthreads();

    auto produce = [&](int s, int st) {
        if (tid == 0) {
            uint32_t mba = s ? mb1 : mb0;
            mbar_expect(mba, 2 * KVBYTES);
            uint32_t* buf = KV0 + s * KVW;
            bulkcp(sm2u(buf), &g_kk[(((size_t)bh * 32 + st) * 32) * 72], KVBYTES, mba);
            bulkcp(sm2u(buf + 32 * KVB),
                   &g_vk[(((size_t)bh * 32 + st) * 32) * 72], KVBYTES, mba);
        }
    };

    if (tid == 0) {
        mbar_expect(mbq, 128 * QSB * 4);
        bulkcp(sm2u(Qs), &g_qk[(((size_t)bh * 16 + qt) * 128) * 36], 128 * QSB * 4, mbq);
    }
    produce(0, 0);
    mbar_wait(mbq, 0);

    float m_run[2] = { -1e30f, -1e30f };
    float l_run[2] = { 0.f, 0.f };
    float4 oacc[8];
    #pragma unroll
    for (int i = 0; i < 8; i++) oacc[i] = make_float4(0.f, 0.f, 0.f, 0.f);

    int ph0 = 0, ph1 = 0;
    for (int st = 0; st < 32; st++) {
        const int s = st & 1;
        if (st + 1 < 32) produce(s ^ 1, st + 1);
        if (s == 0) { mbar_wait(mb0, ph0); ph0 ^= 1; }
        else        { mbar_wait(mb1, ph1); ph1 ^= 1; }
        const uint32_t* Kp = KV0 + s * KVW;
        const uint32_t* Vp = Kp + 32 * KVB;

        // ---- scores S = Q @ K^T ----
        float4 sacc[8];
        #pragma unroll
        for (int i = 0; i < 8; i++) sacc[i] = make_float4(0.f, 0.f, 0.f, 0.f);

        #pragma unroll
        for (int ks = 0; ks < 4; ks++) {
            const int kp0 = ks * 8;
            uint32_t a[4];
            ldsm4(a, qsh + (wq * QSB + kp0) * 4 + qoff);
            #pragma unroll
            for (int nt = 0; nt < 8; nt++) {
                uint32_t b0 = Kp[(kp0 + tq) * KVB + nt * 8 + g];
                uint32_t b1 = Kp[(kp0 + 4 + tq) * KVB + nt * 8 + g];
                mma16(sacc[nt], a, b0, b1);
            }
        }

        // ---- online softmax (rows wq+g, wq+g+8) ----
        float tm0 = -1e30f, tm1 = -1e30f;
        #pragma unroll
        for (int nt = 0; nt < 8; nt++) {
            tm0 = fmaxf(tm0, fmaxf(sacc[nt].x, sacc[nt].y));
            tm1 = fmaxf(tm1, fmaxf(sacc[nt].z, sacc[nt].w));
        }
        tm0 = fmaxf(tm0, __shfl_xor_sync(0xffffffffu, tm0, 1));
        tm0 = fmaxf(tm0, __shfl_xor_sync(0xffffffffu, tm0, 2));
        tm1 = fmaxf(tm1, __shfl_xor_sync(0xffffffffu, tm1, 1));
        tm1 = fmaxf(tm1, __shfl_xor_sync(0xffffffffu, tm1, 2));

        float mn0 = fmaxf(m_run[0], tm0);
        float mn1 = fmaxf(m_run[1], tm1);
        float al0 = __expf(m_run[0] - mn0);
        float al1 = __expf(m_run[1] - mn1);
        m_run[0] = mn0; m_run[1] = mn1;

        // P stays in registers as PV A-fragments (FA2 layout identity)
        uint32_t pa[4][4];
        float rs0 = 0.f, rs1 = 0.f;
        #pragma unroll
        for (int nt = 0; nt < 8; nt++) {
            float p0 = __expf(sacc[nt].x - mn0);
            float p1 = __expf(sacc[nt].y - mn0);
            float p2 = __expf(sacc[nt].z - mn1);
            float p3 = __expf(sacc[nt].w - mn1);
            rs0 += p0 + p1; rs1 += p2 + p3;
            int ks2 = nt >> 1;
            if ((nt & 1) == 0) {
                pa[ks2][0] = f2bf2(p0, p1);
                pa[ks2][1] = f2bf2(p2, p3);
            } else {
                pa[ks2][2] = f2bf2(p0, p1);
                pa[ks2][3] = f2bf2(p2, p3);
            }
        }
        rs0 += __shfl_xor_sync(0xffffffffu, rs0, 1);
        rs0 += __shfl_xor_sync(0xffffffffu, rs0, 2);
        rs1 += __shfl_xor_sync(0xffffffffu, rs1, 1);
        rs1 += __shfl_xor_sync(0xffffffffu, rs1, 2);
        l_run[0] = l_run[0] * al0 + rs0;
        l_run[1] = l_run[1] * al1 + rs1;
        #pragma unroll
        for (int nt = 0; nt < 8; nt++) {
            oacc[nt].x *= al0; oacc[nt].y *= al0;
            oacc[nt].z *= al1; oacc[nt].w *= al1;
        }

        // ---- PV: oacc += P @ V  (A from registers) ----
        #pragma unroll
        for (int ks = 0; ks < 4; ks++) {
            const int kp0 = ks * 8;
            #pragma unroll
            for (int nt = 0; nt < 8; nt++) {
                uint32_t b0 = Vp[(kp0 + tq) * KVB + nt * 8 + g];
                uint32_t b1 = Vp[(kp0 + 4 + tq) * KVB + nt * 8 + g];
                mma16(oacc[nt], pa[ks], b0, b1);
            }
        }
        __syncthreads();
    }

    // ---- epilogue: normalize, write ctx tile images [kt][m][20] ----
    const int bb = bh >> 4, h = bh & 15;
    const float inv0 = 1.f / l_run[0];
    const float inv1 = 1.f / l_run[1];
    const int r0 = qt * 128 + wq + g;
    const size_t mrow0 = (size_t)bb * S + r0;
    #pragma unroll
    for (int nt = 0; nt < 8; nt++) {
        int dhp = nt * 4 + tq;
        int dp = h * 32 + dhp;
        size_t base = ((size_t)(dp >> 4) * M + mrow0) * 20 + (dp & 15);
        g_ctk[base]          = f2bf2(oacc[nt].x * inv0, oacc[nt].y * inv0);
        g_ctk[base + 8 * 20] = f2bf2(oacc[nt].z * inv1, oacc[nt].w * inv1);
    }
}

// ============================================================================
// Kernel 3: output projection + bias + residual, LDSM A-frags.
// grid (M/128, 8), block 256, 8 warps 2m x 4n, warp tile 64x32.
// ============================================================================
#define PXB 20
#define POB 136
#define PRJ_XB (128 * PXB * 4)    // 10240
#define PRJ_WB (16 * POB * 4)     // 8704

__global__ __launch_bounds__(256, 2) void proj_tc(
    const float* __restrict__ x,
    const float* __restrict__ bo)
{
    __shared__ __align__(16) uint32_t Xs[2][128 * PXB];
    __shared__ __align__(16) uint32_t Wp[2][16 * POB];
    __shared__ __align__(8)  uint64_t mb[2];

    const int m0 = blockIdx.x * 128;
    const int nb0 = blockIdx.y;              // 128-col block
    const int n0 = nb0 * 128;

    const int tid = threadIdx.x;
    const int w = tid >> 5, lane = tid & 31;
    const int g = lane >> 2, tq = lane & 3;
    const int wm = w >> 2, wn = w & 3;

    const int li = lane & 7, j01 = (lane >> 3) & 1, jhi = lane >> 4;
    const uint32_t aoff = ((j01 * 8 + li) * PXB + jhi * 4) * 4;
    const uint32_t xsh[2] = { sm2u(&Xs[0][0]), sm2u(&Xs[1][0]) };

    const uint32_t mbA0 = sm2u(&mb[0]), mbA1 = sm2u(&mb[1]);
    if (tid == 0) { mbar_init(mbA0, 1); mbar_init(mbA1, 1); }
    FENCE_ASYNC();
    __syncthreads();

    auto produce = [&](int s, int kt) {
        if (tid == 0) {
            uint32_t mba = s ? mbA1 : mbA0;
            mbar_expect(mba, PRJ_XB + PRJ_WB);
            bulkcp(sm2u(&Xs[s][0]), &g_ctk[((size_t)kt * M + m0) * 20], PRJ_XB, mba);
            bulkcp(sm2u(&Wp[s][0]),
                   &g_wok[(((size_t)nb0 * 32 + kt) * 16) * 136], PRJ_WB, mba);
        }
    };

    float4 acc[4][4];
    #pragma unroll
    for (int i = 0; i < 4; i++)
        #pragma unroll
        for (int j = 0; j < 4; j++) acc[i][j] = make_float4(0.f, 0.f, 0.f, 0.f);

    int ph0 = 0, ph1 = 0;
    produce(0, 0);

    for (int kt = 0; kt < 32; kt++) {
        const int s = kt & 1;
        if (kt + 1 < 32) produce(s ^ 1, kt + 1);
        if (s == 0) { mbar_wait(mbA0, ph0); ph0 ^= 1; }
        else        { mbar_wait(mbA1, ph1); ph1 ^= 1; }
        const uint32_t* Wc = Wp[s];
        const uint32_t xb = xsh[s];
        #pragma unroll
        for (int ks = 0; ks < 2; ks++) {
            const int kk = ks * 8;
            uint32_t a[4][4];
            #pragma unroll
            for (int mt = 0; mt < 4; mt++) {
                int rm = wm * 64 + mt * 16;
                ldsm4(a[mt], xb + (rm * PXB + kk) * 4 + aoff);
            }
            #pragma unroll
            for (int nt = 0; nt < 4; nt++) {
                int nbw = wn * 32 + nt * 8;
                uint32_t b0 = Wc[(kk + tq) * POB + nbw + g];
                uint32_t b1 = Wc[(kk + 4 + tq) * POB + nbw + g];
                #pragma unroll
                for (int mt = 0; mt < 4; mt++) mma16(acc[mt][nt], a[mt], b0, b1);
            }
        }
        __syncthreads();
    }

    #pragma unroll
    for (int mt = 0; mt < 4; mt++) {
        int m = m0 + wm * 64 + mt * 16 + g;
        #pragma unroll
        for (int nt = 0; nt < 4; nt++) {
            int col = n0 + wn * 32 + nt * 8 + 2 * tq;
            float2 b2 = *(const float2*)&bo[col];
            float2 x0 = *(const float2*)&x[(size_t)m * D + col];
            float2 x1 = *(const float2*)&x[(size_t)(m + 8) * D + col];
            *(float2*)&g_tmp[(size_t)m * D + col] =
                make_float2(acc[mt][nt].x + b2.x + x0.x, acc[mt][nt].y + b2.y + x0.y);
            *(float2*)&g_tmp[(size_t)(m + 8) * D + col] =
                make_float2(acc[mt][nt].z + b2.x + x1.x, acc[mt][nt].w + b2.y + x1.y);
        }
    }
}

// ============================================================================
// Kernel 4: LayerNorm per row.  grid M, block 256 (4 floats / thread).
// ============================================================================
__global__ __launch_bounds__(256) void ln_kernel(
    const float* __restrict__ gamma,
    const float* __restrict__ beta,
    float* __restrict__ out)
{
    const int row = blockIdx.x;
    const int t = threadIdx.x;
    const float4* src = (const float4*)(g_tmp + (size_t)row * D);
    float4 v = src[t];

    float s = v.x + v.y + v.z + v.w;
    float q = v.x * v.x + v.y * v.y + v.z * v.z + v.w * v.w;
    #pragma unroll
    for (int o = 16; o > 0; o >>= 1) {
        s += __shfl_xor_sync(0xffffffffu, s, o);
        q += __shfl_xor_sync(0xffffffffu, q, o);
    }
    __shared__ float sh[16];
    int w = t >> 5, lane = t & 31;
    if (lane == 0) { sh[w] = s; sh[8 + w] = q; }
    __syncthreads();
    if (t < 32) {
        s = (lane < 8) ? sh[lane] : 0.f;
        q = (lane < 8) ? sh[8 + lane] : 0.f;
        #pragma unroll
        for (int o = 4; o > 0; o >>= 1) {
            s += __shfl_xor_sync(0xffffffffu, s, o);
            q += __shfl_xor_sync(0xffffffffu, q, o);
        }
        if (lane == 0) { sh[0] = s; sh[1] = q; }
    }
    __syncthreads();
    float mu  = sh[0] * (1.f / D);
    float var = sh[1] * (1.f / D) - mu * mu;
    float rstd = rsqrtf(var + EPS);

    float4 g = ((const float4*)gamma)[t];
    float4 bb = ((const float4*)beta)[t];
    float4 o4;
    o4.x = (v.x - mu) * rstd * g.x + bb.x;
    o4.y = (v.y - mu) * rstd * g.y + bb.y;
    o4.z = (v.z - mu) * rstd * g.z + bb.z;
    o4.w = (v.w - mu) * rstd * g.w + bb.w;
    ((float4*)(out + (size_t)row * D))[t] = o4;
}

// ============================================================================
// launcher
// ============================================================================
extern "C" void kernel_launch(void* const* d_in, const int* in_sizes, int n_in,
                              void* d_out, int out_size)
{
    const float* x     = (const float*)d_in[0];
    const float* Wq    = (const float*)d_in[1];
    const float* Wk    = (const float*)d_in[2];
    const float* Wv    = (const float*)d_in[3];
    const float* Wo    = (const float*)d_in[4];
    const float* bo    = (const float*)d_in[5];
    const float* gamma = (const float*)d_in[6];
    const float* beta  = (const float*)d_in[7];
    float* out = (float*)d_out;

    cudaFuncSetAttribute(attn_tc,
                         cudaFuncAttributeMaxDynamicSharedMemorySize, ATTN_SMEM);

    cvt_x_kernel<<<(M * 512) / 256, 256>>>(x);
    cvt_wqkv_kernel<<<(H * 512 * 192) / 256, 256>>>(Wq, Wk, Wv);
    cvt_wo_kernel<<<(512 * 1024) / 256, 256>>>(Wo);
    qkv_tc<<<dim3(M / 128, H), 512>>>();
    vtr_kernel<<<(B * H * 1024 * 32) / 256, 256>>>();
    attn_tc<<<dim3(S / 128, B * H), 256, ATTN_SMEM>>>();
    proj_tc<<<dim3(M / 128, 8), 256>>>(x, bo);
    ln_kernel<<<M, 256>>>(gamma, beta, out);
}